// round 1
// baseline (speedup 1.0000x reference)
#include <cuda_runtime.h>

// Problem dims
#define BATCH 8
#define CDIM 64
#define HEADS 2
#define CHEAD 32
#define IMG 256
#define HW 65536           // 256*256
#define QKV_CH 192

#define NCHUNK 64
#define PART_STRIDE 1088   // 1024 Gram + 32 qnorm + 32 knorm

// Scratch (static device globals; allocation is forbidden)
__device__ float g_qkv[(size_t)BATCH * QKV_CH * HW];   // after 1x1 conv
__device__ float g_dw [(size_t)BATCH * QKV_CH * HW];   // after depthwise
__device__ float g_part[BATCH * HEADS * NCHUNK * PART_STRIDE];
__device__ float g_M[BATCH * CDIM * CDIM];

// ---------------------------------------------------------------------------
// K1: qkv = 1x1 conv.  out[b][o][n] = sum_i W[o][i] * x[b][i][n]
// grid: (2048, 3)  block: 128.  Each block: 256 pixels, 64 output channels.
// ---------------------------------------------------------------------------
__global__ __launch_bounds__(128) void k_qkv(const float* __restrict__ x,
                                             const float* __restrict__ w) {
    const int chunk = blockIdx.y;                 // 0..2 (which 64 outputs)
    const int gp    = blockIdx.x * 256;           // global pixel base
    const int b     = gp >> 16;
    const int n0    = (gp & 65535) + threadIdx.x; // pixel in batch
    __shared__ float sW[64 * 64];
    for (int t = threadIdx.x; t < 64 * 64; t += 128)
        sW[t] = w[(chunk * 64 + (t >> 6)) * 64 + (t & 63)];
    __syncthreads();

    const float* xb = x + (size_t)b * CDIM * HW;
    float acc0[64], acc1[64];
#pragma unroll
    for (int o = 0; o < 64; ++o) { acc0[o] = 0.f; acc1[o] = 0.f; }

#pragma unroll 2
    for (int i = 0; i < 64; ++i) {
        float x0 = xb[(size_t)i * HW + n0];
        float x1 = xb[(size_t)i * HW + n0 + 128];
#pragma unroll
        for (int o = 0; o < 64; ++o) {
            float wv = sW[o * 64 + i];
            acc0[o] += wv * x0;
            acc1[o] += wv * x1;
        }
    }
    float* outb = g_qkv + (size_t)b * QKV_CH * HW + (size_t)chunk * 64 * HW;
#pragma unroll
    for (int o = 0; o < 64; ++o) {
        outb[(size_t)o * HW + n0]       = acc0[o];
        outb[(size_t)o * HW + n0 + 128] = acc1[o];
    }
}

// ---------------------------------------------------------------------------
// K2: depthwise 3x3 conv, zero padding.
// ---------------------------------------------------------------------------
__global__ __launch_bounds__(256) void k_dw(const float* __restrict__ wdw) {
    const int idx = blockIdx.x * 256 + threadIdx.x;   // over B*192*HW
    const int n  = idx & 65535;
    const int bc = idx >> 16;            // b*192 + ch
    const int ch = bc % QKV_CH;
    const int y = n >> 8, xx = n & 255;
    const float* src = g_qkv + (size_t)bc * HW;
    const float* W = wdw + ch * 9;
    float acc = 0.f;
#pragma unroll
    for (int dy = -1; dy <= 1; ++dy) {
        int yy = y + dy;
        if (yy < 0 || yy > 255) continue;
#pragma unroll
        for (int dx = -1; dx <= 1; ++dx) {
            int xc = xx + dx;
            if (xc < 0 || xc > 255) continue;
            acc += W[(dy + 1) * 3 + (dx + 1)] * src[yy * 256 + xc];
        }
    }
    g_dw[idx] = acc;
}

// ---------------------------------------------------------------------------
// K3: Gram partials.  For (b,h): G[c][d] = sum_n q_c[n]*k_d[n]; plus norms.
// grid: (64 chunks, 16 bh)  block: 256.  Chunk = 1024 pixels.
// ---------------------------------------------------------------------------
#define TP 64
__global__ __launch_bounds__(256) void k_gram() {
    const int bh = blockIdx.y;
    const int chunk = blockIdx.x;
    const int b = bh >> 1, hh = bh & 1;
    const float* qb = g_dw + (size_t)b * QKV_CH * HW + (size_t)(hh * CHEAD) * HW;
    const float* kb = qb + (size_t)64 * HW;
    __shared__ float sq[32][TP + 1];
    __shared__ float sk[32][TP + 1];
    const int base = chunk * 1024;

    float acc[4] = {0.f, 0.f, 0.f, 0.f};
    float nacc = 0.f;
    for (int t = 0; t < 1024; t += TP) {
        for (int l = threadIdx.x; l < 32 * TP; l += 256) {
            int cc = l >> 6, pp = l & 63;
            sq[cc][pp] = qb[(size_t)cc * HW + base + t + pp];
            sk[cc][pp] = kb[(size_t)cc * HW + base + t + pp];
        }
        __syncthreads();
#pragma unroll
        for (int j = 0; j < 4; ++j) {
            int cell = threadIdx.x + 256 * j;
            int c = cell >> 5, d = cell & 31;
            float s = 0.f;
#pragma unroll
            for (int pp = 0; pp < TP; ++pp) s += sq[c][pp] * sk[d][pp];
            acc[j] += s;
        }
        if (threadIdx.x < 64) {
            int r = threadIdx.x >> 5, c = threadIdx.x & 31;
            float (*sb)[TP + 1] = r ? sk : sq;
            float s = 0.f;
#pragma unroll
            for (int pp = 0; pp < TP; ++pp) { float v = sb[c][pp]; s += v * v; }
            nacc += s;
        }
        __syncthreads();
    }
    float* out = g_part + (size_t)(bh * NCHUNK + chunk) * PART_STRIDE;
#pragma unroll
    for (int j = 0; j < 4; ++j) out[threadIdx.x + 256 * j] = acc[j];
    if (threadIdx.x < 64) out[1024 + threadIdx.x] = nacc;
}

// ---------------------------------------------------------------------------
// K4: reduce partials -> attn -> 3x topk-masked softmax -> combine -> fold proj
// grid: 8 (per batch)  block: 256
// ---------------------------------------------------------------------------
__global__ __launch_bounds__(256) void k_attn(const float* __restrict__ wproj,
                                              const float* __restrict__ temp,
                                              const float* __restrict__ a1,
                                              const float* __restrict__ a2,
                                              const float* __restrict__ a3) {
    const int b = blockIdx.x;
    __shared__ float sG[2][32][32];
    __shared__ float sN[2][2][32];     // [head][q/k][c]
    __shared__ float sA[2][32][32];    // combined weighted attention

    for (int cell = threadIdx.x; cell < 2048; cell += 256) {
        int hh = cell >> 10, idx = cell & 1023;
        const float* p = g_part + (size_t)((b * 2 + hh) * NCHUNK) * PART_STRIDE + idx;
        float s = 0.f;
        for (int ck = 0; ck < NCHUNK; ++ck) s += p[(size_t)ck * PART_STRIDE];
        sG[hh][idx >> 5][idx & 31] = s;
    }
    for (int t = threadIdx.x; t < 128; t += 256) {
        int hh = t >> 6, r = (t >> 5) & 1, c = t & 31;
        const float* p = g_part + (size_t)((b * 2 + hh) * NCHUNK) * PART_STRIDE
                         + 1024 + r * 32 + c;
        float s = 0.f;
        for (int ck = 0; ck < NCHUNK; ++ck) s += p[(size_t)ck * PART_STRIDE];
        sN[hh][r][c] = s;
    }
    __syncthreads();

    if (threadIdx.x < 64) {
        const int hh = threadIdx.x >> 5, c = threadIdx.x & 31;
        float qn = fmaxf(sqrtf(sN[hh][0][c]), 1e-12f);
        const float tmp = temp[hh];
        float row[32];
#pragma unroll
        for (int d = 0; d < 32; ++d) {
            float kn = fmaxf(sqrtf(sN[hh][1][d]), 1e-12f);
            row[d] = sG[hh][c][d] / (qn * kn) * tmp;
        }
        // exact selection of 24 largest; capture thresholds for k=16,21,24
        float tv[32];
#pragma unroll
        for (int d = 0; d < 32; ++d) tv[d] = row[d];
        float t16 = 0.f, t21 = 0.f, t24 = 0.f, m0 = 0.f;
        for (int r = 0; r < 24; ++r) {
            float mx = -3.4e38f; int mi = 0;
#pragma unroll
            for (int d = 0; d < 32; ++d)
                if (tv[d] > mx) { mx = tv[d]; mi = d; }
            tv[mi] = -3.4e38f;
            if (r == 0)  m0  = mx;
            if (r == 15) t16 = mx;
            if (r == 20) t21 = mx;
            if (r == 23) t24 = mx;
        }
        float e[32];
        float s16 = 0.f, s21 = 0.f, s24 = 0.f;
#pragma unroll
        for (int d = 0; d < 32; ++d) {
            float ev = expf(row[d] - m0);
            e[d] = ev;
            if (row[d] >= t16) s16 += ev;
            if (row[d] >= t21) s21 += ev;
            if (row[d] >= t24) s24 += ev;
        }
        const float w1 = a1[0] / s16, w2 = a2[0] / s21, w3 = a3[0] / s24;
#pragma unroll
        for (int d = 0; d < 32; ++d) {
            float ww = 0.f;
            if (row[d] >= t16) ww += w1;
            if (row[d] >= t21) ww += w2;
            if (row[d] >= t24) ww += w3;
            sA[hh][c][d] = e[d] * ww;
        }
    }
    __syncthreads();

    // M[o][hh*32+d] = sum_cc wproj[o][hh*32+cc] * A[hh][cc][d]
    for (int t = threadIdx.x; t < 4096; t += 256) {
        int o = t >> 6, chn = t & 63;
        int hh = chn >> 5, d = chn & 31;
        float s = 0.f;
#pragma unroll
        for (int cc = 0; cc < 32; ++cc)
            s += wproj[o * 64 + hh * 32 + cc] * sA[hh][cc][d];
        g_M[(b * 64 + o) * 64 + chn] = s;
    }
}

// ---------------------------------------------------------------------------
// K5: y[b][o][n] = sum_ch M[b][o][ch] * v[b][ch][n]   (v = dw channels 128..191)
// grid: 2048  block: 128.  256 pixels/block, all 64 outputs.
// ---------------------------------------------------------------------------
__global__ __launch_bounds__(128) void k_out(float* __restrict__ out) {
    const int gp = blockIdx.x * 256;
    const int b  = gp >> 16;
    const int n0 = (gp & 65535) + threadIdx.x;
    __shared__ float sM[64 * 64];
    for (int t = threadIdx.x; t < 4096; t += 128) sM[t] = g_M[b * 4096 + t];
    __syncthreads();

    const float* vb = g_dw + (size_t)b * QKV_CH * HW + (size_t)128 * HW;
    float acc0[64], acc1[64];
#pragma unroll
    for (int o = 0; o < 64; ++o) { acc0[o] = 0.f; acc1[o] = 0.f; }

#pragma unroll 2
    for (int ch = 0; ch < 64; ++ch) {
        float v0 = vb[(size_t)ch * HW + n0];
        float v1 = vb[(size_t)ch * HW + n0 + 128];
#pragma unroll
        for (int o = 0; o < 64; ++o) {
            float wv = sM[o * 64 + ch];
            acc0[o] += wv * v0;
            acc1[o] += wv * v1;
        }
    }
    float* ob = out + (size_t)b * CDIM * HW;
#pragma unroll
    for (int o = 0; o < 64; ++o) {
        ob[(size_t)o * HW + n0]       = acc0[o];
        ob[(size_t)o * HW + n0 + 128] = acc1[o];
    }
}

// ---------------------------------------------------------------------------
extern "C" void kernel_launch(void* const* d_in, const int* in_sizes, int n_in,
                              void* d_out, int out_size) {
    (void)in_sizes; (void)n_in; (void)out_size;
    const float* x     = (const float*)d_in[0];
    const float* wqkv  = (const float*)d_in[1];
    const float* wdw   = (const float*)d_in[2];
    const float* wproj = (const float*)d_in[3];
    const float* temp  = (const float*)d_in[4];
    const float* a1    = (const float*)d_in[5];
    const float* a2    = (const float*)d_in[6];
    const float* a3    = (const float*)d_in[7];

    k_qkv <<<dim3(2048, 3), 128>>>(x, wqkv);
    k_dw  <<<393216, 256>>>(wdw);
    k_gram<<<dim3(NCHUNK, BATCH * HEADS), 256>>>();
    k_attn<<<BATCH, 256>>>(wproj, temp, a1, a2, a3);
    k_out <<<2048, 128>>>((float*)d_out);
}

// round 3
// speedup vs baseline: 1.2821x; 1.2821x over previous
#include <cuda_runtime.h>

#define BATCH 8
#define CDIM 64
#define HEADS 2
#define CHEAD 32
#define HW 65536
#define QKV_CH 192

#define NCHUNK 16
#define PART_STRIDE 1088   // 1024 Gram + 32 qnorm + 32 knorm

// Scratch (allocation forbidden -> device globals)
__device__ float g_qkv[(size_t)BATCH * QKV_CH * HW];
__device__ float g_dw [(size_t)BATCH * QKV_CH * HW];
__device__ float g_part[BATCH * HEADS * NCHUNK * PART_STRIDE];
__device__ float g_M[BATCH * CDIM * CDIM];

typedef unsigned long long u64;

__device__ __forceinline__ void fma2(u64 &d, u64 a, u64 b) {
    asm("fma.rn.f32x2 %0, %1, %2, %0;" : "+l"(d) : "l"(a), "l"(b));
}
__device__ __forceinline__ u64 dup2(float v) {
    unsigned int b = __float_as_uint(v);
    return ((u64)b << 32) | b;
}
__device__ __forceinline__ float sum2(u64 p) {
    return __uint_as_float((unsigned int)(p >> 32)) + __uint_as_float((unsigned int)p);
}

// ---------------------------------------------------------------------------
// K1: qkv 1x1 conv. Block: 256-px tile (smem), 128 threads (2 px each),
// 6 chunks of 32 output channels. Packed f32x2 math.
// ---------------------------------------------------------------------------
__global__ __launch_bounds__(128) void k_qkv(const float* __restrict__ x,
                                             const float* __restrict__ w) {
    __shared__ float sx[64 * 256];
    __shared__ u64 sw[64 * 32];            // [i][o] lane-duplicated weights
    const int gp = blockIdx.x * 256;
    const int b = gp >> 16, base = gp & 65535;
    const float* xb = x + (size_t)b * CDIM * HW + base;

    for (int t = threadIdx.x; t < 4096; t += 128) {
        int i = t >> 6, p4 = t & 63;
        ((float4*)sx)[t] = ((const float4*)(xb + (size_t)i * HW))[p4];
    }

    float* outb = g_qkv + (size_t)b * QKV_CH * HW + base + 2 * threadIdx.x;

    for (int c = 0; c < 6; ++c) {
        __syncthreads();
        for (int t = threadIdx.x; t < 2048; t += 128) {
            int o = t & 31, i = t >> 5;
            sw[i * 32 + o] = dup2(w[(c * 32 + o) * 64 + i]);
        }
        __syncthreads();

        u64 acc[32];
#pragma unroll
        for (int o = 0; o < 32; ++o) acc[o] = 0ull;

#pragma unroll 4
        for (int i = 0; i < 64; ++i) {
            u64 xp = *(const u64*)&sx[i * 256 + 2 * threadIdx.x];
#pragma unroll
            for (int o = 0; o < 32; ++o) fma2(acc[o], sw[i * 32 + o], xp);
        }
        float* oc = outb + (size_t)(c * 32) * HW;
#pragma unroll
        for (int o = 0; o < 32; ++o)
            *(u64*)(oc + (size_t)o * HW) = acc[o];
    }
}

// ---------------------------------------------------------------------------
// K2: depthwise 3x3, float4 per thread.
// ---------------------------------------------------------------------------
__global__ __launch_bounds__(256) void k_dw(const float* __restrict__ wdw) {
    const int idx4 = blockIdx.x * 256 + threadIdx.x;      // B*192*HW/4
    const int p4 = idx4 & 16383;
    const int bc = idx4 >> 14;
    const int ch = bc % QKV_CH;
    const int y = p4 >> 6, x0 = (p4 & 63) * 4;
    const float* src = g_qkv + (size_t)bc * HW;
    const float* W = wdw + ch * 9;
    float4 acc = make_float4(0.f, 0.f, 0.f, 0.f);
#pragma unroll
    for (int dy = -1; dy <= 1; ++dy) {
        int yy = y + dy;
        if (yy < 0 || yy > 255) continue;
        const float* row = src + yy * 256;
        float4 cv = *(const float4*)(row + x0);
        float l = (x0 > 0)   ? row[x0 - 1] : 0.f;
        float r = (x0 < 252) ? row[x0 + 4] : 0.f;
        float w0 = W[(dy + 1) * 3 + 0], w1 = W[(dy + 1) * 3 + 1], w2 = W[(dy + 1) * 3 + 2];
        acc.x += w0 * l    + w1 * cv.x + w2 * cv.y;
        acc.y += w0 * cv.x + w1 * cv.y + w2 * cv.z;
        acc.z += w0 * cv.y + w1 * cv.z + w2 * cv.w;
        acc.w += w0 * cv.z + w1 * cv.w + w2 * r;
    }
    ((float4*)g_dw)[idx4] = acc;
}

// ---------------------------------------------------------------------------
// K3: Gram partials, packed pairs. grid (NCHUNK=16, 16 bh), block 256.
// Chunk = 4096 px. Each thread: 2x2 cell block.
// ---------------------------------------------------------------------------
__global__ __launch_bounds__(256) void k_gram() {
    const int bh = blockIdx.y, chunk = blockIdx.x;
    const int b = bh >> 1, hh = bh & 1;
    const float* qb = g_dw + (size_t)b * QKV_CH * HW + (size_t)(hh * CHEAD) * HW;
    const float* kb = qb + (size_t)64 * HW;
    __shared__ u64 sq[32][33];
    __shared__ u64 sk[32][33];
    const int base = chunk * 4096;
    const int c0 = (threadIdx.x >> 4) * 2, d0 = (threadIdx.x & 15) * 2;

    u64 a00 = 0, a01 = 0, a10 = 0, a11 = 0, nacc = 0;
    const int r = threadIdx.x >> 5, cn = threadIdx.x & 31;

    for (int tile = 0; tile < 64; ++tile) {
        const int tb = base + tile * 64;
        for (int t = threadIdx.x; t < 2048; t += 256) {
            int half = t >> 10, l = t & 1023;
            int cc = l >> 5, pp = l & 31;
            const float* src = half ? kb : qb;
            u64 val = *(const u64*)&src[(size_t)cc * HW + tb + 2 * pp];
            if (half) sk[cc][pp] = val; else sq[cc][pp] = val;
        }
        __syncthreads();
#pragma unroll
        for (int pp = 0; pp < 32; ++pp) {
            u64 q0 = sq[c0][pp], q1 = sq[c0 + 1][pp];
            u64 k0 = sk[d0][pp], k1 = sk[d0 + 1][pp];
            fma2(a00, q0, k0); fma2(a01, q0, k1);
            fma2(a10, q1, k0); fma2(a11, q1, k1);
        }
        if (threadIdx.x < 64) {
#pragma unroll
            for (int pp = 0; pp < 32; ++pp) {
                u64 v = r ? sk[cn][pp] : sq[cn][pp];
                fma2(nacc, v, v);
            }
        }
        __syncthreads();
    }
    float* out = g_part + (size_t)(bh * NCHUNK + chunk) * PART_STRIDE;
    out[(c0    ) * 32 + d0    ] = sum2(a00);
    out[(c0    ) * 32 + d0 + 1] = sum2(a01);
    out[(c0 + 1) * 32 + d0    ] = sum2(a10);
    out[(c0 + 1) * 32 + d0 + 1] = sum2(a11);
    if (threadIdx.x < 64) out[1024 + threadIdx.x] = sum2(nacc);
}

// ---------------------------------------------------------------------------
// K4: reduce -> attn -> 3x topk softmax -> combine -> fold proj into M
// ---------------------------------------------------------------------------
__global__ __launch_bounds__(256) void k_attn(const float* __restrict__ wproj,
                                              const float* __restrict__ temp,
                                              const float* __restrict__ a1,
                                              const float* __restrict__ a2,
                                              const float* __restrict__ a3) {
    const int b = blockIdx.x;
    __shared__ float sG[2][32][32];
    __shared__ float sN[2][2][32];
    __shared__ float sA[2][32][32];

    for (int cell = threadIdx.x; cell < 2048; cell += 256) {
        int hh = cell >> 10, idx = cell & 1023;
        const float* p = g_part + (size_t)((b * 2 + hh) * NCHUNK) * PART_STRIDE + idx;
        float s = 0.f;
#pragma unroll
        for (int ck = 0; ck < NCHUNK; ++ck) s += p[(size_t)ck * PART_STRIDE];
        sG[hh][idx >> 5][idx & 31] = s;
    }
    for (int t = threadIdx.x; t < 128; t += 256) {
        int hh = t >> 6, rr = (t >> 5) & 1, c = t & 31;
        const float* p = g_part + (size_t)((b * 2 + hh) * NCHUNK) * PART_STRIDE
                         + 1024 + rr * 32 + c;
        float s = 0.f;
#pragma unroll
        for (int ck = 0; ck < NCHUNK; ++ck) s += p[(size_t)ck * PART_STRIDE];
        sN[hh][rr][c] = s;
    }
    __syncthreads();

    if (threadIdx.x < 64) {
        const int hh = threadIdx.x >> 5, c = threadIdx.x & 31;
        float qn = fmaxf(sqrtf(sN[hh][0][c]), 1e-12f);
        const float tmp = temp[hh];
        float row[32];
#pragma unroll
        for (int d = 0; d < 32; ++d) {
            float kn = fmaxf(sqrtf(sN[hh][1][d]), 1e-12f);
            row[d] = sG[hh][c][d] / (qn * kn) * tmp;
        }
        float tv[32];
#pragma unroll
        for (int d = 0; d < 32; ++d) tv[d] = row[d];
        float t16 = 0.f, t21 = 0.f, t24 = 0.f, m0 = 0.f;
        for (int rr = 0; rr < 24; ++rr) {
            float mx = -3.4e38f; int mi = 0;
#pragma unroll
            for (int d = 0; d < 32; ++d)
                if (tv[d] > mx) { mx = tv[d]; mi = d; }
            tv[mi] = -3.4e38f;
            if (rr == 0)  m0  = mx;
            if (rr == 15) t16 = mx;
            if (rr == 20) t21 = mx;
            if (rr == 23) t24 = mx;
        }
        float e[32];
        float s16 = 0.f, s21 = 0.f, s24 = 0.f;
#pragma unroll
        for (int d = 0; d < 32; ++d) {
            float ev = expf(row[d] - m0);
            e[d] = ev;
            if (row[d] >= t16) s16 += ev;
            if (row[d] >= t21) s21 += ev;
            if (row[d] >= t24) s24 += ev;
        }
        const float w1 = a1[0] / s16, w2 = a2[0] / s21, w3 = a3[0] / s24;
#pragma unroll
        for (int d = 0; d < 32; ++d) {
            float ww = 0.f;
            if (row[d] >= t16) ww += w1;
            if (row[d] >= t21) ww += w2;
            if (row[d] >= t24) ww += w3;
            sA[hh][c][d] = e[d] * ww;
        }
    }
    __syncthreads();

    for (int t = threadIdx.x; t < 4096; t += 256) {
        int o = t >> 6, chn = t & 63;
        int hh = chn >> 5, d = chn & 31;
        float s = 0.f;
#pragma unroll
        for (int cc = 0; cc < 32; ++cc)
            s += wproj[o * 64 + hh * 32 + cc] * sA[hh][cc][d];
        g_M[(b * 64 + o) * 64 + chn] = s;
    }
}

// ---------------------------------------------------------------------------
// K5: y = M @ v. Block: 256-px v tile in smem, 128 threads, 2 chunks of 32 out.
// ---------------------------------------------------------------------------
__global__ __launch_bounds__(128) void k_out(float* __restrict__ out) {
    __shared__ float sv[64 * 256];
    __shared__ u64 sM2[64 * 32];
    const int gp = blockIdx.x * 256;
    const int b = gp >> 16, base = gp & 65535;
    const float* vb = g_dw + (size_t)b * QKV_CH * HW + (size_t)128 * HW + base;

    for (int t = threadIdx.x; t < 4096; t += 128) {
        int i = t >> 6, p4 = t & 63;
        ((float4*)sv)[t] = ((const float4*)(vb + (size_t)i * HW))[p4];
    }

    float* ob = out + (size_t)b * CDIM * HW + base + 2 * threadIdx.x;

    for (int c = 0; c < 2; ++c) {
        __syncthreads();
        for (int t = threadIdx.x; t < 2048; t += 128) {
            int oo = t & 31, ch = t >> 5;
            sM2[ch * 32 + oo] = dup2(g_M[(b * 64 + c * 32 + oo) * 64 + ch]);
        }
        __syncthreads();

        u64 acc[32];
#pragma unroll
        for (int o = 0; o < 32; ++o) acc[o] = 0ull;

#pragma unroll 4
        for (int ch = 0; ch < 64; ++ch) {
            u64 vp = *(const u64*)&sv[ch * 256 + 2 * threadIdx.x];
#pragma unroll
            for (int o = 0; o < 32; ++o) fma2(acc[o], sM2[ch * 32 + o], vp);
        }
        float* oc = ob + (size_t)(c * 32) * HW;
#pragma unroll
        for (int o = 0; o < 32; ++o)
            *(u64*)(oc + (size_t)o * HW) = acc[o];
    }
}

// ---------------------------------------------------------------------------
extern "C" void kernel_launch(void* const* d_in, const int* in_sizes, int n_in,
                              void* d_out, int out_size) {
    (void)in_sizes; (void)n_in; (void)out_size;
    const float* x     = (const float*)d_in[0];
    const float* wqkv  = (const float*)d_in[1];
    const float* wdw   = (const float*)d_in[2];
    const float* wproj = (const float*)d_in[3];
    const float* temp  = (const float*)d_in[4];
    const float* a1    = (const float*)d_in[5];
    const float* a2    = (const float*)d_in[6];
    const float* a3    = (const float*)d_in[7];

    k_qkv <<<2048, 128>>>(x, wqkv);
    k_dw  <<<98304, 256>>>(wdw);
    k_gram<<<dim3(NCHUNK, BATCH * HEADS), 256>>>();
    k_attn<<<BATCH, 256>>>(wproj, temp, a1, a2, a3);
    k_out <<<2048, 128>>>((float*)d_out);
}

// round 5
// speedup vs baseline: 1.6971x; 1.3237x over previous
#include <cuda_runtime.h>
#include <cuda_fp16.h>

#define BATCH 8
#define CDIM 64
#define HEADS 2
#define CHEAD 32
#define HW 65536
#define QKV_CH 192

#define NCHUNK 16
#define PART_STRIDE 1088   // 1024 Gram + 32 qnorm + 32 knorm

// Scratch (allocation forbidden -> device globals). fp16 intermediates.
__device__ __half g_qkv_h[(size_t)BATCH * QKV_CH * HW];
__device__ __half g_dw_h [(size_t)BATCH * QKV_CH * HW];
__device__ float  g_part[BATCH * HEADS * NCHUNK * PART_STRIDE];
__device__ float  g_M[BATCH * CDIM * CDIM];

typedef unsigned long long u64;

__device__ __forceinline__ void fma2(u64 &d, u64 a, u64 b) {
    asm("fma.rn.f32x2 %0, %1, %2, %0;" : "+l"(d) : "l"(a), "l"(b));
}
__device__ __forceinline__ u64 dup2(float v) {
    unsigned int bb = __float_as_uint(v);
    return ((u64)bb << 32) | bb;
}
__device__ __forceinline__ u64 pack2(float lo, float hi) {
    return (u64)__float_as_uint(lo) | ((u64)__float_as_uint(hi) << 32);
}
__device__ __forceinline__ float lo2(u64 p) { return __uint_as_float((unsigned int)p); }
__device__ __forceinline__ float hi2(u64 p) { return __uint_as_float((unsigned int)(p >> 32)); }

// ---------------------------------------------------------------------------
// K1: qkv 1x1 conv. 256 threads, 256-px tile, thread tile 8px x 8out,
// 3 chunks of 64 output channels. fp32 math (f32x2), fp16 stores.
// ---------------------------------------------------------------------------
__global__ __launch_bounds__(256, 2) void k_qkv(const float* __restrict__ x,
                                                const float* __restrict__ w) {
    __shared__ float sx[64 * 256];     // [i][px]
    __shared__ u64 sw[64 * 64];        // [i][o] lane-duplicated
    const int gp = blockIdx.x * 256;
    const int b = gp >> 16, base = gp & 65535;
    const float* xb = x + (size_t)b * CDIM * HW + base;

    for (int t = threadIdx.x; t < 4096; t += 256) {
        int i = t >> 6, p4 = t & 63;
        ((float4*)sx)[t] = ((const float4*)(xb + (size_t)i * HW))[p4];
    }

    const int og = threadIdx.x >> 5, pg = threadIdx.x & 31;

    for (int c = 0; c < 3; ++c) {
        __syncthreads();
        for (int t = threadIdx.x; t < 4096; t += 256) {
            int o = t & 63, i = t >> 6;
            sw[t] = dup2(w[(c * 64 + o) * 64 + i]);
        }
        __syncthreads();

        u64 acc[8][4];
#pragma unroll
        for (int o = 0; o < 8; ++o)
#pragma unroll
            for (int s = 0; s < 4; ++s) acc[o][s] = 0ull;

#pragma unroll 4
        for (int i = 0; i < 64; ++i) {
            u64 xp[4];
#pragma unroll
            for (int s = 0; s < 4; ++s)
                xp[s] = *(const u64*)&sx[i * 256 + pg * 2 + s * 64];
#pragma unroll
            for (int o = 0; o < 8; ++o) {
                u64 wv = sw[i * 64 + og * 8 + o];
#pragma unroll
                for (int s = 0; s < 4; ++s) fma2(acc[o][s], wv, xp[s]);
            }
        }
#pragma unroll
        for (int o = 0; o < 8; ++o) {
            int ch = c * 64 + og * 8 + o;
            __half* dst = g_qkv_h + ((size_t)b * QKV_CH + ch) * HW + base;
#pragma unroll
            for (int s = 0; s < 4; ++s)
                *(__half2*)&dst[pg * 2 + s * 64] =
                    __floats2half2_rn(lo2(acc[o][s]), hi2(acc[o][s]));
        }
    }
}

// ---------------------------------------------------------------------------
// K2: depthwise 3x3, fp16 in/out, 8 px per thread, fp32 math.
// ---------------------------------------------------------------------------
__global__ __launch_bounds__(256) void k_dw(const float* __restrict__ wdw) {
    const int gid = blockIdx.x * 256 + threadIdx.x;     // B*192*HW/8
    const int p8 = gid & 8191;
    const int bc = gid >> 13;
    const int ch = bc % QKV_CH;
    const int y = p8 >> 5, x0 = (p8 & 31) * 8;
    const __half* src = g_qkv_h + (size_t)bc * HW;
    const float* W = wdw + ch * 9;
    float acc[8];
#pragma unroll
    for (int j = 0; j < 8; ++j) acc[j] = 0.f;

#pragma unroll
    for (int dy = -1; dy <= 1; ++dy) {
        int yy = y + dy;
        if (yy < 0 || yy > 255) continue;
        const __half* row = src + yy * 256 + x0;
        uint4 raw = *(const uint4*)row;
        float cv[8];
        {
            float2 f;
            f = __half22float2(*(__half2*)&raw.x); cv[0] = f.x; cv[1] = f.y;
            f = __half22float2(*(__half2*)&raw.y); cv[2] = f.x; cv[3] = f.y;
            f = __half22float2(*(__half2*)&raw.z); cv[4] = f.x; cv[5] = f.y;
            f = __half22float2(*(__half2*)&raw.w); cv[6] = f.x; cv[7] = f.y;
        }
        float l = (x0 > 0)   ? __half2float(row[-1]) : 0.f;
        float r = (x0 < 248) ? __half2float(row[8])  : 0.f;
        float w0 = W[(dy + 1) * 3 + 0], w1 = W[(dy + 1) * 3 + 1], w2 = W[(dy + 1) * 3 + 2];
        acc[0] += w0 * l     + w1 * cv[0] + w2 * cv[1];
#pragma unroll
        for (int j = 1; j < 7; ++j)
            acc[j] += w0 * cv[j - 1] + w1 * cv[j] + w2 * cv[j + 1];
        acc[7] += w0 * cv[6] + w1 * cv[7] + w2 * r;
    }
    uint4 outp;
    *(__half2*)&outp.x = __floats2half2_rn(acc[0], acc[1]);
    *(__half2*)&outp.y = __floats2half2_rn(acc[2], acc[3]);
    *(__half2*)&outp.z = __floats2half2_rn(acc[4], acc[5]);
    *(__half2*)&outp.w = __floats2half2_rn(acc[6], acc[7]);
    *(uint4*)(g_dw_h + (size_t)bc * HW + y * 256 + x0) = outp;
}

// ---------------------------------------------------------------------------
// K3: Gram partials from fp16 q,k. grid (16 chunks, 16 bh), block 256.
// Chunk = 4096 px. Thread: 2x2 cells, packed-pair math.
// ---------------------------------------------------------------------------
__global__ __launch_bounds__(256) void k_gram() {
    const int bh = blockIdx.y, chunk = blockIdx.x;
    const int b = bh >> 1, hh = bh & 1;
    const __half* qb = g_dw_h + (size_t)b * QKV_CH * HW + (size_t)(hh * CHEAD) * HW;
    const __half* kb = qb + (size_t)64 * HW;
    __shared__ u64 sq[32][33];
    __shared__ u64 sk[32][33];
    const int base = chunk * 4096;
    const int c0 = (threadIdx.x >> 4) * 2, d0 = (threadIdx.x & 15) * 2;
    const int r = threadIdx.x >> 5, cn = threadIdx.x & 31;

    u64 a00 = 0, a01 = 0, a10 = 0, a11 = 0, nacc = 0;

    for (int tile = 0; tile < 64; ++tile) {
        const int tb = base + tile * 64;
        // fill: 4 halfs per load -> two packed f32 pairs (pixels 2*pp2 .. 2*pp2+3)
        for (int t = threadIdx.x; t < 1024; t += 256) {
            int half_ = t >> 9, l = t & 511;
            int cc = l >> 4, pp2 = (l & 15) * 2;
            const __half* src = half_ ? kb : qb;
            uint2 raw = *(const uint2*)&src[(size_t)cc * HW + tb + 2 * pp2];
            float2 f0 = __half22float2(*(__half2*)&raw.x);
            float2 f1 = __half22float2(*(__half2*)&raw.y);
            u64* dst = half_ ? &sk[cc][pp2] : &sq[cc][pp2];
            dst[0] = pack2(f0.x, f0.y);
            dst[1] = pack2(f1.x, f1.y);
        }
        __syncthreads();
#pragma unroll
        for (int pp = 0; pp < 32; ++pp) {
            u64 q0 = sq[c0][pp], q1 = sq[c0 + 1][pp];
            u64 k0 = sk[d0][pp], k1 = sk[d0 + 1][pp];
            fma2(a00, q0, k0); fma2(a01, q0, k1);
            fma2(a10, q1, k0); fma2(a11, q1, k1);
        }
        if (threadIdx.x < 64) {
#pragma unroll
            for (int pp = 0; pp < 32; ++pp) {
                u64 v = r ? sk[cn][pp] : sq[cn][pp];
                fma2(nacc, v, v);
            }
        }
        __syncthreads();
    }
    float* out = g_part + (size_t)(bh * NCHUNK + chunk) * PART_STRIDE;
    out[(c0    ) * 32 + d0    ] = lo2(a00) + hi2(a00);
    out[(c0    ) * 32 + d0 + 1] = lo2(a01) + hi2(a01);
    out[(c0 + 1) * 32 + d0    ] = lo2(a10) + hi2(a10);
    out[(c0 + 1) * 32 + d0 + 1] = lo2(a11) + hi2(a11);
    if (threadIdx.x < 64) out[1024 + threadIdx.x] = lo2(nacc) + hi2(nacc);
}

// ---------------------------------------------------------------------------
// K4: reduce -> attn -> 3x topk softmax -> combine -> fold proj into M
// grid: 16 (one per b,h)
// ---------------------------------------------------------------------------
__global__ __launch_bounds__(256) void k_attn(const float* __restrict__ wproj,
                                              const float* __restrict__ temp,
                                              const float* __restrict__ a1,
                                              const float* __restrict__ a2,
                                              const float* __restrict__ a3) {
    const int bh = blockIdx.x;
    const int b = bh >> 1, hh = bh & 1;
    __shared__ float sG[32][32];
    __shared__ float sN[2][32];
    __shared__ float sA[32][32];

    for (int cell = threadIdx.x; cell < 1024; cell += 256) {
        const float* p = g_part + (size_t)(bh * NCHUNK) * PART_STRIDE + cell;
        float s = 0.f;
#pragma unroll
        for (int ck = 0; ck < NCHUNK; ++ck) s += p[(size_t)ck * PART_STRIDE];
        sG[cell >> 5][cell & 31] = s;
    }
    if (threadIdx.x < 64) {
        int rr = threadIdx.x >> 5, c = threadIdx.x & 31;
        const float* p = g_part + (size_t)(bh * NCHUNK) * PART_STRIDE + 1024 + rr * 32 + c;
        float s = 0.f;
#pragma unroll
        for (int ck = 0; ck < NCHUNK; ++ck) s += p[(size_t)ck * PART_STRIDE];
        sN[rr][c] = s;
    }
    __syncthreads();

    if (threadIdx.x < 32) {
        const int c = threadIdx.x;
        float qn = fmaxf(sqrtf(sN[0][c]), 1e-12f);
        const float tmp = temp[hh];
        float row[32];
#pragma unroll
        for (int d = 0; d < 32; ++d) {
            float kn = fmaxf(sqrtf(sN[1][d]), 1e-12f);
            row[d] = sG[c][d] / (qn * kn) * tmp;
        }
        float tv[32];
#pragma unroll
        for (int d = 0; d < 32; ++d) tv[d] = row[d];
        float t16 = 0.f, t21 = 0.f, t24 = 0.f, m0 = 0.f;
        for (int rr = 0; rr < 24; ++rr) {
            float mx = -3.4e38f; int mi = 0;
#pragma unroll
            for (int d = 0; d < 32; ++d)
                if (tv[d] > mx) { mx = tv[d]; mi = d; }
            tv[mi] = -3.4e38f;
            if (rr == 0)  m0  = mx;
            if (rr == 15) t16 = mx;
            if (rr == 20) t21 = mx;
            if (rr == 23) t24 = mx;
        }
        float e[32];
        float s16 = 0.f, s21 = 0.f, s24 = 0.f;
#pragma unroll
        for (int d = 0; d < 32; ++d) {
            float ev = expf(row[d] - m0);
            e[d] = ev;
            if (row[d] >= t16) s16 += ev;
            if (row[d] >= t21) s21 += ev;
            if (row[d] >= t24) s24 += ev;
        }
        const float w1 = a1[0] / s16, w2 = a2[0] / s21, w3 = a3[0] / s24;
#pragma unroll
        for (int d = 0; d < 32; ++d) {
            float ww = 0.f;
            if (row[d] >= t16) ww += w1;
            if (row[d] >= t21) ww += w2;
            if (row[d] >= t24) ww += w3;
            sA[c][d] = e[d] * ww;
        }
    }
    __syncthreads();

    // M[o][hh*32+d] = sum_cc wproj[o][hh*32+cc] * A[cc][d]
    for (int t = threadIdx.x; t < 2048; t += 256) {
        int o = t >> 5, d = t & 31;
        float s = 0.f;
#pragma unroll
        for (int cc = 0; cc < 32; ++cc)
            s += wproj[o * 64 + hh * 32 + cc] * sA[cc][d];
        g_M[(b * 64 + o) * 64 + hh * 32 + d] = s;
    }
}

// ---------------------------------------------------------------------------
// K5: y = M @ v. 256 threads, 256-px tile, thread tile 8px x 8out (one pass).
// ---------------------------------------------------------------------------
__global__ __launch_bounds__(256, 2) void k_out(float* __restrict__ out) {
    __shared__ u64 sv[64 * 128];       // [ch][p2] f32 pairs
    __shared__ u64 sM[64 * 64];        // [ch][o] dup2
    const int gp = blockIdx.x * 256;
    const int b = gp >> 16, base = gp & 65535;
    const __half* vb = g_dw_h + ((size_t)b * QKV_CH + 128) * HW + base;

    for (int t = threadIdx.x; t < 2048; t += 256) {
        int ch = t >> 5, p8 = t & 31;
        uint4 raw = *(const uint4*)&vb[(size_t)ch * HW + p8 * 8];
        float2 f0 = __half22float2(*(__half2*)&raw.x);
        float2 f1 = __half22float2(*(__half2*)&raw.y);
        float2 f2 = __half22float2(*(__half2*)&raw.z);
        float2 f3 = __half22float2(*(__half2*)&raw.w);
        u64* dst = &sv[ch * 128 + p8 * 4];
        dst[0] = pack2(f0.x, f0.y);
        dst[1] = pack2(f1.x, f1.y);
        dst[2] = pack2(f2.x, f2.y);
        dst[3] = pack2(f3.x, f3.y);
    }
    for (int t = threadIdx.x; t < 4096; t += 256) {
        int o = t & 63, ch = t >> 6;
        sM[ch * 64 + o] = dup2(g_M[(b * 64 + o) * 64 + ch]);
    }
    __syncthreads();

    const int og = threadIdx.x >> 5, pg = threadIdx.x & 31;
    u64 acc[8][4];
#pragma unroll
    for (int o = 0; o < 8; ++o)
#pragma unroll
        for (int s = 0; s < 4; ++s) acc[o][s] = 0ull;

#pragma unroll 4
    for (int ch = 0; ch < 64; ++ch) {
        u64 xp[4];
#pragma unroll
        for (int s = 0; s < 4; ++s)
            xp[s] = sv[ch * 128 + pg + s * 32];
#pragma unroll
        for (int o = 0; o < 8; ++o) {
            u64 wv = sM[ch * 64 + og * 8 + o];
#pragma unroll
            for (int s = 0; s < 4; ++s) fma2(acc[o][s], wv, xp[s]);
        }
    }
#pragma unroll
    for (int o = 0; o < 8; ++o) {
        int ochan = og * 8 + o;
        float* dst = out + ((size_t)b * CDIM + ochan) * HW + base;
#pragma unroll
        for (int s = 0; s < 4; ++s)
            *(float2*)&dst[pg * 2 + s * 64] = make_float2(lo2(acc[o][s]), hi2(acc[o][s]));
    }
}

// ---------------------------------------------------------------------------
extern "C" void kernel_launch(void* const* d_in, const int* in_sizes, int n_in,
                              void* d_out, int out_size) {
    (void)in_sizes; (void)n_in; (void)out_size;
    const float* x     = (const float*)d_in[0];
    const float* wqkv  = (const float*)d_in[1];
    const float* wdw   = (const float*)d_in[2];
    const float* wproj = (const float*)d_in[3];
    const float* temp  = (const float*)d_in[4];
    const float* a1    = (const float*)d_in[5];
    const float* a2    = (const float*)d_in[6];
    const float* a3    = (const float*)d_in[7];

    k_qkv <<<2048, 256>>>(x, wqkv);
    k_dw  <<<49152, 256>>>(wdw);
    k_gram<<<dim3(NCHUNK, BATCH * HEADS), 256>>>();
    k_attn<<<BATCH * HEADS, 256>>>(wproj, temp, a1, a2, a3);
    k_out <<<2048, 256>>>((float*)d_out);
}